// round 8
// baseline (speedup 1.0000x reference)
#include <cuda_runtime.h>

// SparseBiasDiagUnfolder — one wave, 146 blocks x 896 threads (28 warps/CTA),
// 2 window-rows per warp, div-free index math.
//
//   adj: (B=2, N=2048, N=2048, F=16) fp32; starts 0,4,...,2040 (511);
//   out (B, 511, 56*16).
//
// 8176 rows, 2 per warp -> 4088 warps = 146 x 28 exactly (one wave).
// Warp w covers rows [2w, 2w+2); both share bs = w>>2 (b*511+s), bs<1022 so
// b = (bs>=511), s = bs - 511*b — no integer division. Each row is 512B
// contiguous: lane l loads float4 base+l -> 2 independent fully-coalesced
// LDG.128 batched up front. Stores: 28 active lanes/row, contiguous 448B run.

namespace {
constexpr int N        = 2048;
constexpr int NSTARTS  = 511;
constexpr int WARPS_PER_BLOCK = 28;
constexpr int THREADS  = WARPS_PER_BLOCK * 32;   // 896
constexpr int BLOCKS   = 146;                    // 4088 warps = 8176 rows / 2
}

__global__ void __launch_bounds__(THREADS)
sparse_diag_unfold_kernel(const float4* __restrict__ adj, float4* __restrict__ out)
{
    const int gt   = blockIdx.x * THREADS + threadIdx.x;
    const int w    = gt >> 5;                 // 0..4087
    const int lane = gt & 31;

    const int bs      = w >> 2;               // b*511 + s, < 1022
    const int ii_base = (w & 3) * 2;          // 0,2,4,6

    const int b = (bs >= NSTARTS);            // no division
    const int s = bs - b * NSTARTS;

    // float4 base index of row (bs, ii_base)
    const long base0 = (long)b * (N * N * 4)
                     + (long)s * ((N + 1) * 16)
                     + ii_base * (N * 4)
                     + lane;

    const int jj = lane >> 2;
    const int v  = lane & 3;

    // 2 independent coalesced 512B loads, batched (MLP_p1 = 2).
    float4 vals[2];
    #pragma unroll
    for (int k = 0; k < 2; k++)
        vals[k] = adj[base0 + k * (N * 4)];

    const long out_base = (long)bs * (56 * 4);
    #pragma unroll
    for (int k = 0; k < 2; k++) {
        const int ii = ii_base + k;
        if (jj != ii) {
            const int pos = ii * 7 + jj - (jj > ii);   // 0..55
            out[out_base + pos * 4 + v] = vals[k];
        }
    }
}

extern "C" void kernel_launch(void* const* d_in, const int* in_sizes, int n_in,
                              void* d_out, int out_size)
{
    const float4* adj = (const float4*)d_in[0];
    float4* out = (float4*)d_out;
    sparse_diag_unfold_kernel<<<BLOCKS, THREADS>>>(adj, out);
}

// round 9
// speedup vs baseline: 1.0246x; 1.0246x over previous
#include <cuda_runtime.h>

// SparseBiasDiagUnfolder — final: one wave, 146 x 896 (28 warps/CTA),
// 2 window-rows per warp, div-free and fully 32-bit index math.
//
//   adj: (B=2, N=2048, N=2048, F=16) fp32; starts 0,4,...,2040 (511);
//   out (B, 511, 56*16).
//
// Max float4 index into adj = 2*2048*2048*4 = 2^25  -> fits in 32-bit.
// Max float4 index into out = 228,927               -> fits in 32-bit.
// Warp w covers rows [2w, 2w+2), both share bs = w>>2 = b*511+s (bs<1022,
// so b = bs>=511: no division). Each row is a 512B contiguous run: lane l
// loads float4 base+l -> 2 independent fully-coalesced LDG.128 batched up
// front. Stores: 28 active lanes/row write a contiguous 448B run
// (diagonal chunk dropped, pos = ii*7 + jj - (jj>ii)).

namespace {
constexpr int N        = 2048;
constexpr int NSTARTS  = 511;
constexpr int WARPS_PER_BLOCK = 28;
constexpr int THREADS  = WARPS_PER_BLOCK * 32;   // 896
constexpr int BLOCKS   = 146;                    // 4088 warps = 8176 rows / 2
}

__global__ void __launch_bounds__(THREADS)
sparse_diag_unfold_kernel(const float4* __restrict__ adj, float4* __restrict__ out)
{
    const unsigned gt   = blockIdx.x * THREADS + threadIdx.x;
    const unsigned w    = gt >> 5;                 // 0..4087
    const unsigned lane = gt & 31;

    const unsigned bs      = w >> 2;               // b*511 + s, < 1022
    const unsigned ii_base = (w & 3) * 2;          // 0,2,4,6

    const unsigned b = (bs >= NSTARTS);            // no division
    const unsigned s = bs - b * NSTARTS;

    // 32-bit float4 base index of row (bs, ii_base):
    //   b*N*N*4 + s*(N+1)*16 + ii_base*N*4 + lane   (max ~2^25)
    const unsigned base0 = b * (N * N * 4u)
                         + s * ((N + 1) * 16u)
                         + ii_base * (N * 4u)
                         + lane;

    const unsigned jj = lane >> 2;
    const unsigned v  = lane & 3;

    // 2 independent coalesced 512B loads, batched (MLP_p1 = 2).
    float4 vals[2];
    #pragma unroll
    for (int k = 0; k < 2; k++)
        vals[k] = adj[base0 + (unsigned)k * (N * 4u)];

    const unsigned out_base = bs * (56u * 4u);
    #pragma unroll
    for (int k = 0; k < 2; k++) {
        const unsigned ii = ii_base + k;
        if (jj != ii) {
            const unsigned pos = ii * 7u + jj - (jj > ii);   // 0..55
            out[out_base + pos * 4u + v] = vals[k];
        }
    }
}

extern "C" void kernel_launch(void* const* d_in, const int* in_sizes, int n_in,
                              void* d_out, int out_size)
{
    const float4* adj = (const float4*)d_in[0];
    float4* out = (float4*)d_out;
    sparse_diag_unfold_kernel<<<BLOCKS, THREADS>>>(adj, out);
}